// round 10
// baseline (speedup 1.0000x reference)
#include <cuda_runtime.h>
#include <cuda_bf16.h>

#define Bb   8
#define T    16
#define C    64
#define Hh   56
#define Ww   56
#define HW   3136          // 56*56
#define HW4  784           // HW/4
#define DIN  64            // 8*8 pooled
#define DOUT 32            // 2*d_t
#define NBC  512           // b*c
#define NT   (NBC * T)     // 8192 (n,t) slices
#define NCOL (NBC * HW4)   // 401408 float4 columns (= 1568 * 256)

// scratch: pooled features [n*T+t][64], 2MB
__device__ float g_flat[NT * DIN];

// ---------------------------------------------------------------------------
// Kernel 1: pooling, warp-autonomous. One block per (n,t) slice; each warp
// owns one bin-row (7 image rows x 56 cols). ~5.5 TB/s = read ceiling.
// ---------------------------------------------------------------------------
__global__ __launch_bounds__(256)
void pool_kernel(const float* __restrict__ x)
{
    const int nt   = blockIdx.x;        // n*T + t
    const int n    = nt >> 4;
    const int t    = nt & 15;
    const int b    = n >> 6;
    const int c    = n & 63;
    const int wid  = threadIdx.x >> 5;  // d1 = bin row, 0..7
    const int lane = threadIdx.x & 31;

    __shared__ float scol[8][56 + 8];   // per-warp column sums (padded)

    const float* slice = x + ((size_t)(b * T + t) * C + c) * HW;
    const float2* rows = (const float2*)(slice + (7 * wid) * Ww);  // 28 f2/row

    if (lane < 28) {
        float2 s = make_float2(0.f, 0.f);
        #pragma unroll
        for (int dh = 0; dh < 7; ++dh) {
            const float2 v = rows[dh * (Ww / 2) + lane];
            s.x += v.x;
            s.y += v.y;
        }
        scol[wid][2 * lane]     = s.x;
        scol[wid][2 * lane + 1] = s.y;
    }
    __syncwarp();

    if (lane < 8) {
        const float* cs = &scol[wid][7 * lane];
        float a0 = cs[0] + cs[1];
        float a1 = cs[2] + cs[3];
        float a2 = cs[4] + cs[5];
        a0 += cs[6];
        g_flat[nt * DIN + wid * 8 + lane] = (a0 + a1 + a2) * (1.f / 49.f);
    }
}

// ---------------------------------------------------------------------------
// Kernel 2 (fused): per-block att recompute for its <=2 n's, then
// out[b,t,c,:] = sum_s att[n,t,s] * x[b,s,c,:].
// Flattened grid (1568 full blocks), REVERSED n order for L2 reuse of x,
// float4 per thread, __stcs streaming stores.
// ---------------------------------------------------------------------------
__global__ __launch_bounds__(256)
void av_fused_kernel(const float* __restrict__ x, float* __restrict__ out,
                     const float* __restrict__ Wq, const float* __restrict__ bq,
                     const float* __restrict__ Wk, const float* __restrict__ bk)
{
    const int tid  = threadIdx.x;
    const int gid0 = blockIdx.x << 8;               // first column of block
    const int n0   = gid0 / HW4;                    // block spans n0 or n0+1

    __shared__ float sWq[DIN * DOUT];               // 8 KB
    __shared__ float sWk[DIN * DOUT];               // 8 KB
    __shared__ float flat[2][T][DIN];               // 8 KB
    __shared__ float sq[2][T][DOUT + 1];
    __shared__ float sk[2][T][DOUT + 1];
    __shared__ float satt[2][T * T];

    // ---- stage weights + pooled features for the 2 reversed-n's ----
    for (int i = tid; i < DIN * DOUT; i += 256) {
        sWq[i] = Wq[i];
        sWk[i] = Wk[i];
    }
    #pragma unroll
    for (int mm = 0; mm < 2; ++mm) {
        const int nn = n0 + mm;
        const int rn = (nn < NBC) ? (NBC - 1 - nn) : 0;
        for (int i = tid; i < T * DIN; i += 256)
            ((float*)flat[mm])[i] = g_flat[rn * T * DIN + i];
    }
    __syncthreads();

    // ---- q/k projection: 2 n's x 512 outputs = 4 per thread ----
    #pragma unroll
    for (int mm = 0; mm < 2; ++mm) {
        for (int i = tid; i < T * DOUT; i += 256) {
            const int tt = i >> 5, j = i & 31;
            float aq = bq[j];
            float ak = bk[j];
            #pragma unroll
            for (int d = 0; d < DIN; ++d) {
                const float f = flat[mm][tt][d];
                aq = fmaf(f, sWq[d * DOUT + j], aq);
                ak = fmaf(f, sWk[d * DOUT + j], ak);
            }
            sq[mm][tt][j] = aq;
            sk[mm][tt][j] = ak;
        }
    }
    __syncthreads();

    // ---- logits + shuffle softmax, per m ----
    {
        const int i = tid >> 4, j = tid & 15;
        #pragma unroll
        for (int mm = 0; mm < 2; ++mm) {
            float s = 0.f;
            #pragma unroll
            for (int d = 0; d < DOUT; ++d)
                s = fmaf(sq[mm][i][d], sk[mm][j][d], s);
            s *= 0.25f;                              // 1/sqrt(16)
            float mx = s;
            #pragma unroll
            for (int k = 8; k >= 1; k >>= 1)
                mx = fmaxf(mx, __shfl_xor_sync(0xffffffffu, mx, k));
            float e = __expf(s - mx);
            float ssum = e;
            #pragma unroll
            for (int k = 8; k >= 1; k >>= 1)
                ssum += __shfl_xor_sync(0xffffffffu, ssum, k);
            satt[mm][tid] = e * (1.f / ssum);
        }
    }
    __syncthreads();

    // ---- main AV: one float4 column per thread ----
    const int gid = gid0 + tid;
    const int n   = gid / HW4;
    const int p4  = gid - n * HW4;
    const int m   = n - n0;
    const int rn  = NBC - 1 - n;                    // reversed n
    const int b   = rn >> 6;
    const int c   = rn & 63;

    const int stride_s = C * HW4;                   // float4 stride per t/s
    const int base     = (b * T * C + c) * HW4 + p4;
    const float4* xb = (const float4*)x + base;
    float4* ob = (float4*)out + base;

    float4 v[T];
    #pragma unroll
    for (int s = 0; s < T; ++s)
        v[s] = xb[s * stride_s];

    const float* arow = satt[m];
    #pragma unroll
    for (int t = 0; t < T; ++t) {
        float4 a = make_float4(0.f, 0.f, 0.f, 0.f);
        #pragma unroll
        for (int s = 0; s < T; ++s) {
            const float w = arow[t * T + s];
            a.x = fmaf(w, v[s].x, a.x);
            a.y = fmaf(w, v[s].y, a.y);
            a.z = fmaf(w, v[s].z, a.z);
            a.w = fmaf(w, v[s].w, a.w);
        }
        __stcs(&ob[t * stride_s], a);               // streaming store
    }
}

// ---------------------------------------------------------------------------
extern "C" void kernel_launch(void* const* d_in, const int* in_sizes, int n_in,
                              void* d_out, int out_size)
{
    const float* x  = (const float*)d_in[0];
    const float* Wq = (const float*)d_in[1];
    const float* bq = (const float*)d_in[2];
    const float* Wk = (const float*)d_in[3];
    const float* bk = (const float*)d_in[4];
    float* out = (float*)d_out;

    pool_kernel<<<NT, 256>>>(x);
    av_fused_kernel<<<NCOL / 256, 256>>>(x, out, Wq, bq, Wk, bk);
}

// round 11
// speedup vs baseline: 1.7216x; 1.7216x over previous
#include <cuda_runtime.h>
#include <cuda_bf16.h>

#define Bb   8
#define T    16
#define C    64
#define Hh   56
#define Ww   56
#define HW   3136          // 56*56
#define HW4  784           // HW/4
#define DIN  64            // 8*8 pooled
#define DOUT 32            // 2*d_t
#define NBC  512           // b*c
#define NT   (NBC * T)     // 8192 (n,t) slices
#define NCOL (NBC * HW4)   // 401408 float4 columns (= 1568 * 256)

// scratch
__device__ float g_flat[NT * DIN];       // pooled features [n*T+t][64], 2MB
__device__ float g_att[NBC * T * T];     // softmaxed attention, 512KB

// ---------------------------------------------------------------------------
// Kernel 1: pooling, warp-autonomous. One block per (n,t) slice; each warp
// owns one bin-row (7 image rows x 56 cols). ~5.5 TB/s = read ceiling.
// ---------------------------------------------------------------------------
__global__ __launch_bounds__(256)
void pool_kernel(const float* __restrict__ x)
{
    const int nt   = blockIdx.x;        // n*T + t
    const int n    = nt >> 4;
    const int t    = nt & 15;
    const int b    = n >> 6;
    const int c    = n & 63;
    const int wid  = threadIdx.x >> 5;  // d1 = bin row, 0..7
    const int lane = threadIdx.x & 31;

    __shared__ float scol[8][56 + 8];   // per-warp column sums (padded)

    const float* slice = x + ((size_t)(b * T + t) * C + c) * HW;
    const float2* rows = (const float2*)(slice + (7 * wid) * Ww);  // 28 f2/row

    if (lane < 28) {
        float2 s = make_float2(0.f, 0.f);
        #pragma unroll
        for (int dh = 0; dh < 7; ++dh) {
            const float2 v = rows[dh * (Ww / 2) + lane];
            s.x += v.x;
            s.y += v.y;
        }
        scol[wid][2 * lane]     = s.x;
        scol[wid][2 * lane + 1] = s.y;
    }
    __syncwarp();

    if (lane < 8) {
        const float* cs = &scol[wid][7 * lane];
        float a0 = cs[0] + cs[1];
        float a1 = cs[2] + cs[3];
        float a2 = cs[4] + cs[5];
        a0 += cs[6];
        g_flat[nt * DIN + wid * 8 + lane] = (a0 + a1 + a2) * (1.f / 49.f);
    }
}

// ---------------------------------------------------------------------------
// Kernel 2: q/k projection + att + register/shuffle softmax. One block per n.
// PDL: weights staged pre-sync; g_flat read post-sync.
// ---------------------------------------------------------------------------
__global__ __launch_bounds__(256)
void att_kernel(const float* __restrict__ Wq, const float* __restrict__ bq,
                const float* __restrict__ Wk, const float* __restrict__ bk)
{
    const int n   = blockIdx.x;
    const int tid = threadIdx.x;

    __shared__ float flat[T][DIN];           // 4 KB
    __shared__ float sWq[DIN * DOUT];        // 8 KB
    __shared__ float sWk[DIN * DOUT];        // 8 KB
    __shared__ float sq[T][DOUT + 1];
    __shared__ float sk[T][DOUT + 1];

    // pre-sync: pure-input staging (independent of pool's output)
    for (int i = tid; i < DIN * DOUT; i += 256) {
        sWq[i] = Wq[i];
        sWk[i] = Wk[i];
    }

    cudaGridDependencySynchronize();         // wait for pool's g_flat

    for (int i = tid; i < T * DIN; i += 256)
        ((float*)flat)[i] = g_flat[n * T * DIN + i];
    __syncthreads();

    for (int i = tid; i < T * DOUT; i += 256) {
        const int tt = i >> 5, j = i & 31;
        float aq = bq[j];
        float ak = bk[j];
        #pragma unroll
        for (int d = 0; d < DIN; ++d) {
            const float f = flat[tt][d];
            aq = fmaf(f, sWq[d * DOUT + j], aq);
            ak = fmaf(f, sWk[d * DOUT + j], ak);
        }
        sq[tt][j] = aq;
        sk[tt][j] = ak;
    }
    __syncthreads();

    const int i = tid >> 4, j = tid & 15;
    float s = 0.f;
    #pragma unroll
    for (int d = 0; d < DOUT; ++d)
        s = fmaf(sq[i][d], sk[j][d], s);
    s *= 0.25f;                          // 1/sqrt(16)

    float m = s;
    #pragma unroll
    for (int k = 8; k >= 1; k >>= 1)
        m = fmaxf(m, __shfl_xor_sync(0xffffffffu, m, k));
    float e = __expf(s - m);
    float ssum = e;
    #pragma unroll
    for (int k = 8; k >= 1; k >>= 1)
        ssum += __shfl_xor_sync(0xffffffffu, ssum, k);

    g_att[n * (T * T) + tid] = e * (1.f / ssum);
}

// ---------------------------------------------------------------------------
// Kernel 3: out[b,t,c,:] = sum_s att[n,t,s] * x[b,s,c,:]
// PDL: all 16 x-loads issued PRE-sync (x is read-only; only g_att depends on
// att). Reversed n order for L2 reuse of x; __stcs streaming stores.
// ---------------------------------------------------------------------------
__global__ __launch_bounds__(256)
void av_kernel(const float* __restrict__ x, float* __restrict__ out)
{
    const int tid  = threadIdx.x;
    const int gid0 = blockIdx.x << 8;               // first column of block
    const int n0   = gid0 / HW4;                    // block spans n0 or n0+1

    const int gid = gid0 + tid;
    const int n   = gid / HW4;
    const int p4  = gid - n * HW4;
    const int m   = n - n0;
    const int rn  = NBC - 1 - n;                    // reversed n
    const int b   = rn >> 6;
    const int c   = rn & 63;

    const int stride_s = C * HW4;                   // float4 stride per t/s
    const int base     = (b * T * C + c) * HW4 + p4;
    const float4* xb = (const float4*)x + base;
    float4* ob = (float4*)out + base;

    // pre-sync: issue the 16 strided x loads (no dependency on att)
    float4 v[T];
    #pragma unroll
    for (int s = 0; s < T; ++s)
        v[s] = xb[s * stride_s];

    cudaGridDependencySynchronize();                // wait for att's g_att

    // stage att rows for the (at most) 2 reversed-n's this block touches
    __shared__ float satt[2][T * T];
    #pragma unroll
    for (int i = tid; i < 2 * T * T; i += 256) {
        const int mm  = i >> 8;
        const int idx = i & 255;
        const int nn  = n0 + mm;
        satt[mm][idx] = (nn < NBC) ? g_att[(NBC - 1 - nn) * (T * T) + idx] : 0.f;
    }
    __syncthreads();

    const float* arow = satt[m];
    #pragma unroll
    for (int t = 0; t < T; ++t) {
        float4 a = make_float4(0.f, 0.f, 0.f, 0.f);
        #pragma unroll
        for (int s = 0; s < T; ++s) {
            const float w = arow[t * T + s];
            a.x = fmaf(w, v[s].x, a.x);
            a.y = fmaf(w, v[s].y, a.y);
            a.z = fmaf(w, v[s].z, a.z);
            a.w = fmaf(w, v[s].w, a.w);
        }
        __stcs(&ob[t * stride_s], a);               // streaming store
    }
}

// ---------------------------------------------------------------------------
extern "C" void kernel_launch(void* const* d_in, const int* in_sizes, int n_in,
                              void* d_out, int out_size)
{
    const float* x  = (const float*)d_in[0];
    const float* Wq = (const float*)d_in[1];
    const float* bq = (const float*)d_in[2];
    const float* Wk = (const float*)d_in[3];
    const float* bk = (const float*)d_in[4];
    float* out = (float*)d_out;

    pool_kernel<<<NT, 256>>>(x);

    cudaLaunchAttribute attr[1];
    attr[0].id = cudaLaunchAttributeProgrammaticStreamSerialization;
    attr[0].val.programmaticStreamSerializationAllowed = 1;

    {
        cudaLaunchConfig_t cfg = {};
        cfg.gridDim  = dim3(NBC);
        cfg.blockDim = dim3(256);
        cfg.dynamicSmemBytes = 0;
        cfg.stream = 0;
        cfg.attrs = attr;
        cfg.numAttrs = 1;
        cudaLaunchKernelEx(&cfg, att_kernel, Wq, bq, Wk, bk);
    }
    {
        cudaLaunchConfig_t cfg = {};
        cfg.gridDim  = dim3(NCOL / 256);
        cfg.blockDim = dim3(256);
        cfg.dynamicSmemBytes = 0;
        cfg.stream = 0;
        cfg.attrs = attr;
        cfg.numAttrs = 1;
        cudaLaunchKernelEx(&cfg, av_kernel, x, out);
    }
}